// round 1
// baseline (speedup 1.0000x reference)
#include <cuda_runtime.h>
#include <math.h>

#define B_ 8
#define N_ 2048
#define C_ 512
#define H_ 8
#define D_ 64
#define F_ 1536
#define M_ (B_*N_)

// Scratch (allocation-free rule: __device__ globals)
__device__ float g_Q[(size_t)B_*H_*N_*D_];
__device__ float g_K[(size_t)B_*H_*N_*D_];
__device__ float g_V[(size_t)B_*H_*N_*D_];
__device__ float g_ctx[(size_t)B_*N_*C_];

// ---------------------------------------------------------------------------
// Kernel 1: qkv = x @ W_qkv^T, fused RoPE (+scale on Q), scatter to Q/K/V
// Tile 64(M) x 64(F), K-step 16, 256 threads, 4x4 register microtile.
// ---------------------------------------------------------------------------
__global__ __launch_bounds__(256) void qkv_rope_kernel(
    const float* __restrict__ x, const float* __restrict__ Wqkv,
    const int* __restrict__ ncp)
{
    __shared__ float As[16][68];   // As[kk][mm] (transposed), row stride 68 -> 16B aligned
    __shared__ float Bs[16][68];   // Bs[kk][ff]
    const int tx = threadIdx.x, ty = threadIdx.y;
    const int tid = ty*16 + tx;
    const int m0 = blockIdx.y*64, f0 = blockIdx.x*64;
    const int lr = tid >> 2;         // 0..63
    const int lc = (tid & 3) * 4;    // 0,4,8,12

    float acc[4][4] = {};
    for (int k0 = 0; k0 < C_; k0 += 16) {
        float4 av = *(const float4*)(x    + (size_t)(m0+lr)*C_ + k0 + lc);
        float4 bv = *(const float4*)(Wqkv + (size_t)(f0+lr)*C_ + k0 + lc);
        As[lc+0][lr]=av.x; As[lc+1][lr]=av.y; As[lc+2][lr]=av.z; As[lc+3][lr]=av.w;
        Bs[lc+0][lr]=bv.x; Bs[lc+1][lr]=bv.y; Bs[lc+2][lr]=bv.z; Bs[lc+3][lr]=bv.w;
        __syncthreads();
        #pragma unroll
        for (int kk = 0; kk < 16; kk++) {
            float4 a4 = *(const float4*)&As[kk][ty*4];
            float4 b4 = *(const float4*)&Bs[kk][tx*4];
            float ar[4] = {a4.x, a4.y, a4.z, a4.w};
            float br[4] = {b4.x, b4.y, b4.z, b4.w};
            #pragma unroll
            for (int i = 0; i < 4; i++)
                #pragma unroll
                for (int j = 0; j < 4; j++)
                    acc[i][j] = fmaf(ar[i], br[j], acc[i][j]);
        }
        __syncthreads();
    }

    const int nc = ncp ? *ncp : 1;
    #pragma unroll
    for (int i = 0; i < 4; i++) {
        const int m = m0 + ty*4 + i;
        const int b = m / N_;
        const int n = m - b*N_;
        // 4 consecutive f columns never cross an s (512) or h (64) boundary.
        const int fbase = f0 + tx*4;
        const int s = fbase / C_;
        const int rem = fbase - s*C_;
        const int h = rem >> 6;
        const int d0 = rem & 63;       // 4-aligned
        float v[4] = {acc[i][0], acc[i][1], acc[i][2], acc[i][3]};
        if (s < 2 && n >= nc) {        // RoPE for q,k (non-cls tokens)
            const float pos = (float)(n - nc);
            #pragma unroll
            for (int jp = 0; jp < 2; jp++) {
                const int pi = (d0 >> 1) + jp;             // pair index d/2
                const float invf = expf(-(float)pi * (9.210340371976184f/32.f)); // 10000^(-pi/32)
                float sn, cs;
                sincosf(pos * invf, &sn, &cs);
                const float e = v[jp*2], o = v[jp*2+1];
                v[jp*2]   = e*cs - o*sn;
                v[jp*2+1] = e*sn + o*cs;
            }
        }
        if (s == 0) {
            #pragma unroll
            for (int j = 0; j < 4; j++) v[j] *= 0.125f;    // D^-0.5
        }
        float* dst = (s == 0) ? g_Q : (s == 1) ? g_K : g_V;
        const size_t base = ((((size_t)b*H_ + h)*N_ + n)*D_) + d0;
        *(float4*)(dst + base) = make_float4(v[0], v[1], v[2], v[3]);
    }
}

// ---------------------------------------------------------------------------
// Kernel 2: flash attention. CTA = (64-query tile) x (b,h). 64-wide key tiles.
// Row softmax stats live in registers (identical across the 16 tx lanes after
// butterfly reduction). Static smem = 3 * 64*64 * 4B = 48KB exactly.
// ---------------------------------------------------------------------------
__global__ __launch_bounds__(256) void attn_kernel(const float* __restrict__ mask)
{
    __shared__ float QsT[64][64];   // [d][row]
    __shared__ float KsT[64][64];   // [d][key]  (reused as PsT[key? no: P row-major below])
    __shared__ float Vs [64][64];   // [key][d]

    const int qb = blockIdx.x * 64;
    const int bh = blockIdx.y;
    const int b  = bh >> 3;
    const int h  = bh & 7;
    const float* Qg = g_Q + (size_t)bh*N_*D_;
    const float* Kg = g_K + (size_t)bh*N_*D_;
    const float* Vg = g_V + (size_t)bh*N_*D_;
    const float* mrow = mask + (size_t)b*N_;

    const int tx = threadIdx.x, ty = threadIdx.y;
    const int tid = ty*16 + tx;
    const int lr  = tid >> 2;          // 0..63 (row for tile loads)
    const int lc16 = (tid & 3) * 16;   // 0,16,32,48

    // Load Q tile transposed: QsT[d][row]
    {
        const float* src = Qg + (size_t)(qb+lr)*D_ + lc16;
        #pragma unroll
        for (int u = 0; u < 4; u++) {
            float4 q = *(const float4*)(src + u*4);
            const int c = lc16 + u*4;
            QsT[c+0][lr]=q.x; QsT[c+1][lr]=q.y; QsT[c+2][lr]=q.z; QsT[c+3][lr]=q.w;
        }
    }

    float O[4][4] = {};
    float rmax[4] = {-1e30f, -1e30f, -1e30f, -1e30f};
    float rsum[4] = {};

    for (int k0 = 0; k0 < N_; k0 += 64) {
        __syncthreads();   // prior-iteration smem reads done (also covers Q store 1st iter)
        {
            const float* ks = Kg + (size_t)(k0+lr)*D_ + lc16;
            const float* vs = Vg + (size_t)(k0+lr)*D_ + lc16;
            #pragma unroll
            for (int u = 0; u < 4; u++) {
                float4 kv = *(const float4*)(ks + u*4);
                const int c = lc16 + u*4;
                KsT[c+0][lr]=kv.x; KsT[c+1][lr]=kv.y; KsT[c+2][lr]=kv.z; KsT[c+3][lr]=kv.w;
                *(float4*)&Vs[lr][c] = *(const float4*)(vs + u*4);
            }
        }
        __syncthreads();

        // S = Q * K^T (Q pre-scaled)
        float S[4][4] = {};
        #pragma unroll 8
        for (int d = 0; d < 64; d++) {
            float4 q4 = *(const float4*)&QsT[d][ty*4];
            float4 k4 = *(const float4*)&KsT[d][tx*4];
            float q[4] = {q4.x, q4.y, q4.z, q4.w};
            float k[4] = {k4.x, k4.y, k4.z, k4.w};
            #pragma unroll
            for (int i = 0; i < 4; i++)
                #pragma unroll
                for (int j = 0; j < 4; j++)
                    S[i][j] = fmaf(q[i], k[j], S[i][j]);
        }
        // + key mask (query-side mask term cancels in softmax)
        float mj[4];
        #pragma unroll
        for (int j = 0; j < 4; j++) mj[j] = mrow[k0 + tx*4 + j];
        #pragma unroll
        for (int i = 0; i < 4; i++)
            #pragma unroll
            for (int j = 0; j < 4; j++) S[i][j] += mj[j];

        // Row max across 16 tx lanes (butterfly — stays in the 16-lane group)
        float tmax[4];
        #pragma unroll
        for (int i = 0; i < 4; i++)
            tmax[i] = fmaxf(fmaxf(S[i][0], S[i][1]), fmaxf(S[i][2], S[i][3]));
        #pragma unroll
        for (int off = 1; off < 16; off <<= 1)
            #pragma unroll
            for (int i = 0; i < 4; i++)
                tmax[i] = fmaxf(tmax[i], __shfl_xor_sync(0xffffffffu, tmax[i], off));

        float fac[4], tsum[4];
        #pragma unroll
        for (int i = 0; i < 4; i++) {
            const float nm = fmaxf(rmax[i], tmax[i]);
            fac[i] = __expf(rmax[i] - nm);
            rmax[i] = nm;
            float ts = 0.f;
            #pragma unroll
            for (int j = 0; j < 4; j++) {
                S[i][j] = __expf(S[i][j] - nm);
                ts += S[i][j];
            }
            tsum[i] = ts;
        }
        #pragma unroll
        for (int off = 1; off < 16; off <<= 1)
            #pragma unroll
            for (int i = 0; i < 4; i++)
                tsum[i] += __shfl_xor_sync(0xffffffffu, tsum[i], off);
        #pragma unroll
        for (int i = 0; i < 4; i++) {
            rsum[i] = rsum[i]*fac[i] + tsum[i];
            #pragma unroll
            for (int j = 0; j < 4; j++) O[i][j] *= fac[i];
        }

        __syncthreads();                 // all KsT reads done; reuse as P (row-major)
        float (*Ps)[64] = KsT;
        #pragma unroll
        for (int i = 0; i < 4; i++)
            *(float4*)&Ps[ty*4+i][tx*4] = make_float4(S[i][0], S[i][1], S[i][2], S[i][3]);
        __syncthreads();

        // O += P @ V
        #pragma unroll 8
        for (int m = 0; m < 64; m++) {
            float p[4];
            #pragma unroll
            for (int i = 0; i < 4; i++) p[i] = Ps[ty*4+i][m];
            float4 v4 = *(const float4*)&Vs[m][tx*4];
            float v[4] = {v4.x, v4.y, v4.z, v4.w};
            #pragma unroll
            for (int i = 0; i < 4; i++)
                #pragma unroll
                for (int j = 0; j < 4; j++)
                    O[i][j] = fmaf(p[i], v[j], O[i][j]);
        }
    }

    // Write ctx as [B, N, H*D] so the projection is a plain GEMM
    #pragma unroll
    for (int i = 0; i < 4; i++) {
        const int r = ty*4 + i;
        const float inv = 1.f / rsum[i];
        const int n = qb + r;
        *(float4*)(g_ctx + ((size_t)b*N_ + n)*C_ + h*D_ + tx*4) =
            make_float4(O[i][0]*inv, O[i][1]*inv, O[i][2]*inv, O[i][3]*inv);
    }
}

// ---------------------------------------------------------------------------
// Kernel 3: out = ctx @ W_proj^T + b_proj
// ---------------------------------------------------------------------------
__global__ __launch_bounds__(256) void proj_kernel(
    const float* __restrict__ Wp, const float* __restrict__ bp,
    float* __restrict__ out)
{
    __shared__ float As[16][68];
    __shared__ float Bs[16][68];
    const int tx = threadIdx.x, ty = threadIdx.y;
    const int tid = ty*16 + tx;
    const int m0 = blockIdx.y*64, f0 = blockIdx.x*64;
    const int lr = tid >> 2;
    const int lc = (tid & 3) * 4;

    float acc[4][4] = {};
    for (int k0 = 0; k0 < C_; k0 += 16) {
        float4 av = *(const float4*)(g_ctx + (size_t)(m0+lr)*C_ + k0 + lc);
        float4 bv = *(const float4*)(Wp    + (size_t)(f0+lr)*C_ + k0 + lc);
        As[lc+0][lr]=av.x; As[lc+1][lr]=av.y; As[lc+2][lr]=av.z; As[lc+3][lr]=av.w;
        Bs[lc+0][lr]=bv.x; Bs[lc+1][lr]=bv.y; Bs[lc+2][lr]=bv.z; Bs[lc+3][lr]=bv.w;
        __syncthreads();
        #pragma unroll
        for (int kk = 0; kk < 16; kk++) {
            float4 a4 = *(const float4*)&As[kk][ty*4];
            float4 b4 = *(const float4*)&Bs[kk][tx*4];
            float ar[4] = {a4.x, a4.y, a4.z, a4.w};
            float br[4] = {b4.x, b4.y, b4.z, b4.w};
            #pragma unroll
            for (int i = 0; i < 4; i++)
                #pragma unroll
                for (int j = 0; j < 4; j++)
                    acc[i][j] = fmaf(ar[i], br[j], acc[i][j]);
        }
        __syncthreads();
    }

    float4 bias = *(const float4*)(bp + f0 + tx*4);
    #pragma unroll
    for (int i = 0; i < 4; i++) {
        const int m = m0 + ty*4 + i;
        *(float4*)(out + (size_t)m*C_ + f0 + tx*4) =
            make_float4(acc[i][0]+bias.x, acc[i][1]+bias.y,
                        acc[i][2]+bias.z, acc[i][3]+bias.w);
    }
}

// ---------------------------------------------------------------------------
extern "C" void kernel_launch(void* const* d_in, const int* in_sizes, int n_in,
                              void* d_out, int out_size)
{
    const float* x    = (const float*)d_in[0];
    const float* mask = (const float*)d_in[1];
    const float* Wqkv = (const float*)d_in[2];
    const float* Wp   = (const float*)d_in[3];
    const float* bp   = (const float*)d_in[4];
    const int*   ncp  = (n_in > 5) ? (const int*)d_in[5] : nullptr;

    dim3 blk(16, 16);
    qkv_rope_kernel<<<dim3(F_/64, M_/64), blk>>>(x, Wqkv, ncp);
    attn_kernel   <<<dim3(N_/64, B_*H_),  blk>>>(mask);
    proj_kernel   <<<dim3(C_/64, M_/64),  blk>>>(Wp, bp, (float*)d_out);
}

// round 2
// speedup vs baseline: 3.0198x; 3.0198x over previous
#include <cuda_runtime.h>
#include <math.h>
#include <stdint.h>

#define B_ 8
#define N_ 2048
#define C_ 512
#define H_ 8
#define D_ 64
#define F_ 1536
#define M_ (B_*N_)

// Scratch (allocation-free rule: __device__ globals)
__device__ float g_Q[(size_t)B_*H_*N_*D_];
__device__ float g_K[(size_t)B_*H_*N_*D_];
__device__ float g_V[(size_t)B_*H_*N_*D_];
__device__ float g_ctx[(size_t)B_*N_*C_];

// ---------------------------------------------------------------------------
// helpers
// ---------------------------------------------------------------------------
__device__ __forceinline__ float tf32r(float x) {
    float y;
    asm("cvt.rna.tf32.f32 %0, %1;" : "=f"(y) : "f"(x));
    return y;
}

__device__ __forceinline__ void mma_tf32(float* c, const uint32_t* a, const uint32_t* b) {
    asm volatile(
        "mma.sync.aligned.m16n8k8.row.col.f32.tf32.tf32.f32 "
        "{%0,%1,%2,%3},{%4,%5,%6,%7},{%8,%9},{%0,%1,%2,%3};\n"
        : "+f"(c[0]), "+f"(c[1]), "+f"(c[2]), "+f"(c[3])
        : "r"(a[0]), "r"(a[1]), "r"(a[2]), "r"(a[3]), "r"(b[0]), "r"(b[1]));
}

// ---------------------------------------------------------------------------
// Kernel 1: qkv = x @ W_qkv^T (tf32 mma), fused RoPE (+scale Q), scatter Q/K/V
// CTA tile 128(M) x 128(F), k-step 32. 8 warps = 4(M) x 2(F), warp tile 32x64.
// ---------------------------------------------------------------------------
__global__ __launch_bounds__(256) void qkv_mma_kernel(
    const float* __restrict__ x, const float* __restrict__ Wqkv,
    const int* __restrict__ ncp)
{
    __shared__ float As[128][36];   // stride 36 (= 4 mod 32): frag gathers conflict-free
    __shared__ float Bs[128][36];

    const int tid  = threadIdx.x;
    const int warp = tid >> 5, lane = tid & 31;
    const int g = lane >> 2, tg = lane & 3;
    const int wm = warp >> 1, wn = warp & 1;
    const int m0 = blockIdx.y * 128, f0 = blockIdx.x * 128;

    float acc[2][8][4] = {};

    const int lrow = tid >> 3;            // 0..31
    const int lcol = (tid & 7) * 4;       // 0..28

    for (int k0 = 0; k0 < C_; k0 += 32) {
        #pragma unroll
        for (int p = 0; p < 4; p++) {
            const int row = lrow + p * 32;
            float4 av = *(const float4*)(x    + (size_t)(m0 + row) * C_ + k0 + lcol);
            float4 bv = *(const float4*)(Wqkv + (size_t)(f0 + row) * C_ + k0 + lcol);
            As[row][lcol+0] = tf32r(av.x); As[row][lcol+1] = tf32r(av.y);
            As[row][lcol+2] = tf32r(av.z); As[row][lcol+3] = tf32r(av.w);
            Bs[row][lcol+0] = tf32r(bv.x); Bs[row][lcol+1] = tf32r(bv.y);
            Bs[row][lcol+2] = tf32r(bv.z); Bs[row][lcol+3] = tf32r(bv.w);
        }
        __syncthreads();

        #pragma unroll
        for (int ks = 0; ks < 32; ks += 8) {
            uint32_t af[2][4];
            #pragma unroll
            for (int mt = 0; mt < 2; mt++) {
                const float* ap = &As[wm*32 + mt*16 + g][ks + tg];
                af[mt][0] = __float_as_uint(ap[0]);
                af[mt][1] = __float_as_uint(ap[8*36]);
                af[mt][2] = __float_as_uint(ap[4]);
                af[mt][3] = __float_as_uint(ap[8*36 + 4]);
            }
            uint32_t bf[8][2];
            #pragma unroll
            for (int nt = 0; nt < 8; nt++) {
                const float* bp2 = &Bs[wn*64 + nt*8 + g][ks + tg];
                bf[nt][0] = __float_as_uint(bp2[0]);
                bf[nt][1] = __float_as_uint(bp2[4]);
            }
            #pragma unroll
            for (int mt = 0; mt < 2; mt++)
                #pragma unroll
                for (int nt = 0; nt < 8; nt++)
                    mma_tf32(acc[mt][nt], af[mt], bf[nt]);
        }
        __syncthreads();
    }

    const int nc = ncp ? *ncp : 1;
    #pragma unroll
    for (int mt = 0; mt < 2; mt++) {
        #pragma unroll
        for (int hh = 0; hh < 2; hh++) {
            const int m = m0 + wm*32 + mt*16 + hh*8 + g;
            const int b = m >> 11, n = m & 2047;
            #pragma unroll
            for (int nt = 0; nt < 8; nt++) {
                const int f = f0 + wn*64 + nt*8 + 2*tg;
                float v0 = acc[mt][nt][hh*2+0], v1 = acc[mt][nt][hh*2+1];
                const int s = f >> 9, rem = f & 511, hd = rem >> 6, d0 = rem & 63;
                if (s < 2 && n >= nc) {
                    const int pi = d0 >> 1;
                    const float invf = expf(-(float)pi * (9.210340371976184f/32.f));
                    float sn, cs;
                    sincosf((float)(n - nc) * invf, &sn, &cs);
                    const float e = v0, o = v1;
                    v0 = e*cs - o*sn;
                    v1 = e*sn + o*cs;
                }
                if (s == 0) { v0 *= 0.125f; v1 *= 0.125f; }
                float* dst = (s == 0) ? g_Q : (s == 1) ? g_K : g_V;
                *(float2*)(dst + ((((size_t)b*H_ + hd)*N_ + n)*D_ + d0)) = make_float2(v0, v1);
            }
        }
    }
}

// ---------------------------------------------------------------------------
// Kernel 2: flash attention with tf32 mma.
// CTA: 128 queries x (b,h), 64-key tiles. 8 warps = 4(q) x 2(k or d).
// Dynamic smem (~106KB): Q/K/V/P tiles + row-stat arrays.
// ---------------------------------------------------------------------------
#define QS_OFF   0
#define KS_OFF   8704        // 128*68
#define VS_OFF   13056       // + 64*68
#define PS_OFF   17664       // + 64*72
#define RMAX_OFF 26368       // + 128*68
#define RFAC_OFF 26496
#define RSUM_OFF 26624
#define REDM_OFF 26752
#define REDS_OFF 27008
#define ATTN_SMEM_FLOATS 27264
#define ATTN_SMEM_BYTES  (ATTN_SMEM_FLOATS*4)

__global__ __launch_bounds__(256) void attn_mma_kernel(const float* __restrict__ mask)
{
    extern __shared__ float sm[];
    float* Qs = sm + QS_OFF;          // [128][68]
    float* Ks = sm + KS_OFF;          // [64][68]
    float* Vs = sm + VS_OFF;          // [64][72]  (stride 72: conflict-free PV B-frags)
    float* Ps = sm + PS_OFF;          // [128][68]
    float* rowMax = sm + RMAX_OFF;
    float* rowFac = sm + RFAC_OFF;
    float* rowSum = sm + RSUM_OFF;
    float* redM = sm + REDM_OFF;      // [2][128]
    float* redS = sm + REDS_OFF;      // [2][128]

    const int tid  = threadIdx.x;
    const int warp = tid >> 5, lane = tid & 31;
    const int g = lane >> 2, tg = lane & 3;
    const int wm = warp >> 1, wn = warp & 1;
    const int qb = blockIdx.x * 128;
    const int bh = blockIdx.y, b = bh >> 3, h = bh & 7;
    const float* Qg = g_Q + (size_t)bh * N_ * D_;
    const float* Kg = g_K + (size_t)bh * N_ * D_;
    const float* Vg = g_V + (size_t)bh * N_ * D_;
    const float* mrow = mask + (size_t)b * N_;

    // Load Q tile (tf32): thread -> row tid/4 (+64), cols (tid%4)*16 .. +15
    {
        const int row = tid >> 2, c0 = (tid & 3) * 16;
        #pragma unroll
        for (int p = 0; p < 2; p++) {
            const float* src = Qg + (size_t)(qb + row + p*64) * D_ + c0;
            float* dst = Qs + (row + p*64) * 68 + c0;
            #pragma unroll
            for (int u = 0; u < 4; u++) {
                float4 v = *(const float4*)(src + u*4);
                dst[u*4+0] = tf32r(v.x); dst[u*4+1] = tf32r(v.y);
                dst[u*4+2] = tf32r(v.z); dst[u*4+3] = tf32r(v.w);
            }
        }
    }
    if (tid < 128) { rowMax[tid] = -1e30f; rowSum[tid] = 0.f; }

    float O[2][4][4] = {};

    for (int k0 = 0; k0 < N_; k0 += 64) {
        __syncthreads();   // prev-iteration smem reads complete (also covers Q/init 1st iter)
        {
            const int row = tid >> 2, c0 = (tid & 3) * 16;
            const float* ksrc = Kg + (size_t)(k0 + row) * D_ + c0;
            const float* vsrc = Vg + (size_t)(k0 + row) * D_ + c0;
            float* kd = Ks + row*68 + c0;
            float* vd = Vs + row*72 + c0;
            #pragma unroll
            for (int u = 0; u < 4; u++) {
                float4 kv = *(const float4*)(ksrc + u*4);
                kd[u*4+0] = tf32r(kv.x); kd[u*4+1] = tf32r(kv.y);
                kd[u*4+2] = tf32r(kv.z); kd[u*4+3] = tf32r(kv.w);
                float4 vv = *(const float4*)(vsrc + u*4);
                vd[u*4+0] = tf32r(vv.x); vd[u*4+1] = tf32r(vv.y);
                vd[u*4+2] = tf32r(vv.z); vd[u*4+3] = tf32r(vv.w);
            }
        }
        __syncthreads();

        // ---- S = Q K^T ----
        float S[2][4][4] = {};
        #pragma unroll
        for (int ks = 0; ks < 64; ks += 8) {
            uint32_t af[2][4];
            #pragma unroll
            for (int mt = 0; mt < 2; mt++) {
                const float* ap = Qs + (wm*32 + mt*16 + g)*68 + ks + tg;
                af[mt][0] = __float_as_uint(ap[0]);
                af[mt][1] = __float_as_uint(ap[8*68]);
                af[mt][2] = __float_as_uint(ap[4]);
                af[mt][3] = __float_as_uint(ap[8*68 + 4]);
            }
            uint32_t bf[4][2];
            #pragma unroll
            for (int nt = 0; nt < 4; nt++) {
                const float* bp2 = Ks + (wn*32 + nt*8 + g)*68 + ks + tg;
                bf[nt][0] = __float_as_uint(bp2[0]);
                bf[nt][1] = __float_as_uint(bp2[4]);
            }
            #pragma unroll
            for (int mt = 0; mt < 2; mt++)
                #pragma unroll
                for (int nt = 0; nt < 4; nt++)
                    mma_tf32(S[mt][nt], af[mt], bf[nt]);
        }

        // ---- + key mask, tile row max (query-side mask term cancels in softmax) ----
        float tmax[2][2] = {{-1e30f,-1e30f},{-1e30f,-1e30f}};
        #pragma unroll
        for (int nt = 0; nt < 4; nt++) {
            const int col = k0 + wn*32 + nt*8 + 2*tg;
            const float mv0 = __ldg(mrow + col), mv1 = __ldg(mrow + col + 1);
            #pragma unroll
            for (int mt = 0; mt < 2; mt++) {
                S[mt][nt][0] += mv0; S[mt][nt][1] += mv1;
                S[mt][nt][2] += mv0; S[mt][nt][3] += mv1;
                tmax[mt][0] = fmaxf(tmax[mt][0], fmaxf(S[mt][nt][0], S[mt][nt][1]));
                tmax[mt][1] = fmaxf(tmax[mt][1], fmaxf(S[mt][nt][2], S[mt][nt][3]));
            }
        }
        #pragma unroll
        for (int o = 1; o < 4; o <<= 1)
            #pragma unroll
            for (int mt = 0; mt < 2; mt++)
                #pragma unroll
                for (int hh = 0; hh < 2; hh++)
                    tmax[mt][hh] = fmaxf(tmax[mt][hh], __shfl_xor_sync(0xffffffffu, tmax[mt][hh], o));
        if (tg == 0) {
            #pragma unroll
            for (int mt = 0; mt < 2; mt++)
                #pragma unroll
                for (int hh = 0; hh < 2; hh++)
                    redM[wn*128 + wm*32 + mt*16 + hh*8 + g] = tmax[mt][hh];
        }
        __syncthreads();
        if (wn == 0 && tg == 0) {
            #pragma unroll
            for (int mt = 0; mt < 2; mt++)
                #pragma unroll
                for (int hh = 0; hh < 2; hh++) {
                    const int r = wm*32 + mt*16 + hh*8 + g;
                    const float nm = fmaxf(rowMax[r], fmaxf(redM[r], redM[128 + r]));
                    rowFac[r] = __expf(rowMax[r] - nm);
                    rowMax[r] = nm;
                }
        }
        __syncthreads();

        // ---- exp, O rescale, P -> smem (tf32), partial row sums ----
        float tsum[2][2] = {};
        #pragma unroll
        for (int mt = 0; mt < 2; mt++) {
            #pragma unroll
            for (int hh = 0; hh < 2; hh++) {
                const int r = wm*32 + mt*16 + hh*8 + g;
                const float nm = rowMax[r], fac = rowFac[r];
                float part = 0.f;
                #pragma unroll
                for (int nt = 0; nt < 4; nt++) {
                    const float p0 = __expf(S[mt][nt][hh*2+0] - nm);
                    const float p1 = __expf(S[mt][nt][hh*2+1] - nm);
                    part += p0 + p1;
                    float* pd = Ps + r*68 + wn*32 + nt*8 + 2*tg;
                    pd[0] = tf32r(p0); pd[1] = tf32r(p1);
                    O[mt][nt][hh*2+0] *= fac;
                    O[mt][nt][hh*2+1] *= fac;
                }
                tsum[mt][hh] = part;
            }
        }
        #pragma unroll
        for (int o = 1; o < 4; o <<= 1)
            #pragma unroll
            for (int mt = 0; mt < 2; mt++)
                #pragma unroll
                for (int hh = 0; hh < 2; hh++)
                    tsum[mt][hh] += __shfl_xor_sync(0xffffffffu, tsum[mt][hh], o);
        if (tg == 0) {
            #pragma unroll
            for (int mt = 0; mt < 2; mt++)
                #pragma unroll
                for (int hh = 0; hh < 2; hh++)
                    redS[wn*128 + wm*32 + mt*16 + hh*8 + g] = tsum[mt][hh];
        }
        __syncthreads();   // Ps + redS ready
        if (wn == 0 && tg == 0) {
            #pragma unroll
            for (int mt = 0; mt < 2; mt++)
                #pragma unroll
                for (int hh = 0; hh < 2; hh++) {
                    const int r = wm*32 + mt*16 + hh*8 + g;
                    rowSum[r] = rowSum[r] * rowFac[r] + redS[r] + redS[128 + r];
                }
        }

        // ---- O += P @ V ----
        #pragma unroll
        for (int kk = 0; kk < 64; kk += 8) {
            uint32_t af[2][4];
            #pragma unroll
            for (int mt = 0; mt < 2; mt++) {
                const float* ap = Ps + (wm*32 + mt*16 + g)*68 + kk + tg;
                af[mt][0] = __float_as_uint(ap[0]);
                af[mt][1] = __float_as_uint(ap[8*68]);
                af[mt][2] = __float_as_uint(ap[4]);
                af[mt][3] = __float_as_uint(ap[8*68 + 4]);
            }
            uint32_t bf[4][2];
            #pragma unroll
            for (int nt = 0; nt < 4; nt++) {
                const float* vp2 = Vs + (kk + tg)*72 + wn*32 + nt*8 + g;
                bf[nt][0] = __float_as_uint(vp2[0]);
                bf[nt][1] = __float_as_uint(vp2[4*72]);
            }
            #pragma unroll
            for (int mt = 0; mt < 2; mt++)
                #pragma unroll
                for (int nt = 0; nt < 4; nt++)
                    mma_tf32(O[mt][nt], af[mt], bf[nt]);
        }
    }
    __syncthreads();   // last rowSum update visible

    // ---- normalize + write ctx as [B, N, H*D] ----
    #pragma unroll
    for (int mt = 0; mt < 2; mt++) {
        #pragma unroll
        for (int hh = 0; hh < 2; hh++) {
            const int r = wm*32 + mt*16 + hh*8 + g;
            const float inv = 1.f / rowSum[r];
            const int n = qb + r;
            #pragma unroll
            for (int nt = 0; nt < 4; nt++) {
                const int d = wn*32 + nt*8 + 2*tg;
                *(float2*)(g_ctx + ((size_t)b*N_ + n)*C_ + h*D_ + d) =
                    make_float2(O[mt][nt][hh*2+0]*inv, O[mt][nt][hh*2+1]*inv);
            }
        }
    }
}

// ---------------------------------------------------------------------------
// Kernel 3: out = ctx @ W_proj^T + b_proj (tf32 mma)
// ---------------------------------------------------------------------------
__global__ __launch_bounds__(256) void proj_mma_kernel(
    const float* __restrict__ Wp, const float* __restrict__ bp,
    float* __restrict__ out)
{
    __shared__ float As[128][36];
    __shared__ float Bs[128][36];

    const int tid  = threadIdx.x;
    const int warp = tid >> 5, lane = tid & 31;
    const int g = lane >> 2, tg = lane & 3;
    const int wm = warp >> 1, wn = warp & 1;
    const int m0 = blockIdx.y * 128, f0 = blockIdx.x * 128;

    float acc[2][8][4] = {};

    const int lrow = tid >> 3;
    const int lcol = (tid & 7) * 4;

    for (int k0 = 0; k0 < C_; k0 += 32) {
        #pragma unroll
        for (int p = 0; p < 4; p++) {
            const int row = lrow + p * 32;
            float4 av = *(const float4*)(g_ctx + (size_t)(m0 + row) * C_ + k0 + lcol);
            float4 bv = *(const float4*)(Wp    + (size_t)(f0 + row) * C_ + k0 + lcol);
            As[row][lcol+0] = tf32r(av.x); As[row][lcol+1] = tf32r(av.y);
            As[row][lcol+2] = tf32r(av.z); As[row][lcol+3] = tf32r(av.w);
            Bs[row][lcol+0] = tf32r(bv.x); Bs[row][lcol+1] = tf32r(bv.y);
            Bs[row][lcol+2] = tf32r(bv.z); Bs[row][lcol+3] = tf32r(bv.w);
        }
        __syncthreads();

        #pragma unroll
        for (int ks = 0; ks < 32; ks += 8) {
            uint32_t af[2][4];
            #pragma unroll
            for (int mt = 0; mt < 2; mt++) {
                const float* ap = &As[wm*32 + mt*16 + g][ks + tg];
                af[mt][0] = __float_as_uint(ap[0]);
                af[mt][1] = __float_as_uint(ap[8*36]);
                af[mt][2] = __float_as_uint(ap[4]);
                af[mt][3] = __float_as_uint(ap[8*36 + 4]);
            }
            uint32_t bf[8][2];
            #pragma unroll
            for (int nt = 0; nt < 8; nt++) {
                const float* bp2 = &Bs[wn*64 + nt*8 + g][ks + tg];
                bf[nt][0] = __float_as_uint(bp2[0]);
                bf[nt][1] = __float_as_uint(bp2[4]);
            }
            #pragma unroll
            for (int mt = 0; mt < 2; mt++)
                #pragma unroll
                for (int nt = 0; nt < 8; nt++)
                    mma_tf32(acc[mt][nt], af[mt], bf[nt]);
        }
        __syncthreads();
    }

    #pragma unroll
    for (int mt = 0; mt < 2; mt++) {
        #pragma unroll
        for (int hh = 0; hh < 2; hh++) {
            const int m = m0 + wm*32 + mt*16 + hh*8 + g;
            #pragma unroll
            for (int nt = 0; nt < 8; nt++) {
                const int f = f0 + wn*64 + nt*8 + 2*tg;
                const float b0v = __ldg(bp + f), b1v = __ldg(bp + f + 1);
                *(float2*)(out + (size_t)m*C_ + f) =
                    make_float2(acc[mt][nt][hh*2+0] + b0v, acc[mt][nt][hh*2+1] + b1v);
            }
        }
    }
}

// ---------------------------------------------------------------------------
extern "C" void kernel_launch(void* const* d_in, const int* in_sizes, int n_in,
                              void* d_out, int out_size)
{
    const float* x    = (const float*)d_in[0];
    const float* mask = (const float*)d_in[1];
    const float* Wqkv = (const float*)d_in[2];
    const float* Wp   = (const float*)d_in[3];
    const float* bp   = (const float*)d_in[4];
    const int*   ncp  = (n_in > 5) ? (const int*)d_in[5] : nullptr;

    cudaFuncSetAttribute(attn_mma_kernel,
                         cudaFuncAttributeMaxDynamicSharedMemorySize, ATTN_SMEM_BYTES);

    qkv_mma_kernel <<<dim3(F_/128, M_/128), 256>>>(x, Wqkv, ncp);
    attn_mma_kernel<<<dim3(N_/128, B_*H_), 256, ATTN_SMEM_BYTES>>>(mask);
    proj_mma_kernel<<<dim3(C_/128, M_/128), 256>>>(Wp, bp, (float*)d_out);
}